// round 5
// baseline (speedup 1.0000x reference)
#include <cuda_runtime.h>
#include <math.h>

#define NNODES 50000
#define NEDGES 800000
#define ETOT   (NEDGES + NNODES)
#define HC     128
#define NOUTC  40
#define NEG_SLOPE 0.2f
#define BN_EPS 1e-5f
#define NSCANB ((NNODES + 1023) / 1024)
#define FULLM 0xffffffffu

// ---------------- scratch (static device arrays; no runtime alloc) ----------
static __device__ __align__(16) float g_h[NNODES * HC];
static __device__ __align__(16) float g_x1[NNODES * HC];
static __device__ __align__(16) float g_x2[NNODES * HC];
static __device__ float g_asrc[NNODES * 2];
static __device__ float g_adst[NNODES * 2];
static __device__ int   g_deg[NNODES];
static __device__ int   g_rowptr[NNODES + 1];
static __device__ int   g_bsum[NSCANB + 1];
static __device__ int   g_tick[ETOT];
static __device__ int   g_csr_src[ETOT];
static __device__ __align__(16) float g_logits[NNODES * NOUTC];
static __device__ int   g_is64;

// ---------------- edge index dtype detection --------------------------------
__global__ void k_detect(const int* ei32) {
    if (threadIdx.x == 0 && blockIdx.x == 0) {
        int any = 0;
        #pragma unroll 1
        for (int i = 0; i < 256; i++) any |= ei32[2 * i + 1];
        g_is64 = (any == 0) ? 1 : 0;   // int64 node ids < 50000 -> high words all 0
    }
}

__device__ __forceinline__ int edge_idx(const void* ei, int pos) {
    if (g_is64) return (int)((const long long*)ei)[pos];
    return ((const int*)ei)[pos];
}

// ---------------- CSR build --------------------------------------------------
__global__ void k_zero() {
    int i = blockIdx.x * blockDim.x + threadIdx.x;
    if (i < NNODES) g_deg[i] = 0;
}

__global__ void k_count(const void* ei) {
    int i = blockIdx.x * blockDim.x + threadIdx.x;
    if (i >= ETOT) return;
    int d = (i < NEDGES) ? edge_idx(ei, NEDGES + i) : (i - NEDGES);
    g_tick[i] = atomicAdd(&g_deg[d], 1);
}

// 3-phase parallel scan
__global__ void k_scan1() {
    __shared__ int s[1024];
    int t = threadIdx.x;
    int idx = blockIdx.x * 1024 + t;
    int v = (idx < NNODES) ? g_deg[idx] : 0;
    s[t] = v;
    __syncthreads();
    #pragma unroll
    for (int o = 1; o < 1024; o <<= 1) {
        int add = (t >= o) ? s[t - o] : 0;
        __syncthreads();
        s[t] += add;
        __syncthreads();
    }
    if (idx < NNODES) g_rowptr[idx + 1] = s[t];
    if (t == 1023) g_bsum[blockIdx.x] = s[1023];
    if (idx == 0) g_rowptr[0] = 0;
}

__global__ void k_scan2() {
    if (threadIdx.x == 0) {
        int acc = 0;
        #pragma unroll 1
        for (int i = 0; i < NSCANB; i++) { int v = g_bsum[i]; g_bsum[i] = acc; acc += v; }
    }
}

__global__ void k_scan3() {
    int idx = blockIdx.x * blockDim.x + threadIdx.x;
    if (idx < NNODES) g_rowptr[idx + 1] += g_bsum[idx >> 10];
}

__global__ void k_fill(const void* ei) {
    int i = blockIdx.x * blockDim.x + threadIdx.x;
    if (i >= ETOT) return;
    int s, d;
    if (i < NEDGES) { s = edge_idx(ei, i); d = edge_idx(ei, NEDGES + i); }
    else            { s = d = i - NEDGES; }
    g_csr_src[g_rowptr[d] + g_tick[i]] = s;   // atomic-free
}

// ---------------- packed-f32x2 SGEMM (K=Nc=128) + fused attention dots -------
__device__ __forceinline__ unsigned long long pack2(float a) {
    unsigned long long r;
    unsigned int u = __float_as_uint(a);
    asm("mov.b64 %0, {%1, %1};" : "=l"(r) : "r"(u));
    return r;
}
__device__ __forceinline__ float2 unpack2(unsigned long long v) {
    float2 f;
    asm("mov.b64 {%0, %1}, %2;" : "=f"(f.x), "=f"(f.y) : "l"(v));
    return f;
}

__global__ __launch_bounds__(256, 2)
void k_sgemm128(const float* __restrict__ A, const float* __restrict__ B,
                float* __restrict__ C, int M,
                const float* __restrict__ att_src, const float* __restrict__ att_dst) {
    __shared__ __align__(16) float As[16][128];   // transposed A tile
    __shared__ __align__(16) float Bs[16][128];
    int t  = threadIdx.x;
    int tx = t & 15, ty = t >> 4;
    int rowBase = blockIdx.x * 128;

    unsigned long long acc[8][4];
    #pragma unroll
    for (int i = 0; i < 8; i++)
        #pragma unroll
        for (int j = 0; j < 4; j++) acc[i][j] = 0ull;

    int aRow = t >> 1;          // 0..127
    int aK   = (t & 1) * 8;     // 0 or 8
    int bRow = t >> 4;          // 0..15
    int bC   = (t & 15) * 8;    // 0..120

    for (int k0 = 0; k0 < 128; k0 += 16) {
        float4 av0 = make_float4(0.f, 0.f, 0.f, 0.f), av1 = av0;
        int gr = rowBase + aRow;
        if (gr < M) {
            const float* ap = A + (size_t)gr * 128 + k0 + aK;
            av0 = *reinterpret_cast<const float4*>(ap);
            av1 = *reinterpret_cast<const float4*>(ap + 4);
        }
        As[aK + 0][aRow] = av0.x; As[aK + 1][aRow] = av0.y;
        As[aK + 2][aRow] = av0.z; As[aK + 3][aRow] = av0.w;
        As[aK + 4][aRow] = av1.x; As[aK + 5][aRow] = av1.y;
        As[aK + 6][aRow] = av1.z; As[aK + 7][aRow] = av1.w;

        const float* bp = B + (size_t)(k0 + bRow) * 128 + bC;
        *reinterpret_cast<float4*>(&Bs[bRow][bC])     = *reinterpret_cast<const float4*>(bp);
        *reinterpret_cast<float4*>(&Bs[bRow][bC + 4]) = *reinterpret_cast<const float4*>(bp + 4);
        __syncthreads();

        #pragma unroll
        for (int k = 0; k < 16; k++) {
            float4 a0 = *reinterpret_cast<const float4*>(&As[k][ty * 8]);
            float4 a1 = *reinterpret_cast<const float4*>(&As[k][ty * 8 + 4]);
            unsigned long long aa[8];
            aa[0] = pack2(a0.x); aa[1] = pack2(a0.y); aa[2] = pack2(a0.z); aa[3] = pack2(a0.w);
            aa[4] = pack2(a1.x); aa[5] = pack2(a1.y); aa[6] = pack2(a1.z); aa[7] = pack2(a1.w);
            const unsigned long long* bpp =
                reinterpret_cast<const unsigned long long*>(&Bs[k][tx * 8]);
            unsigned long long b0 = bpp[0], b1 = bpp[1], b2 = bpp[2], b3 = bpp[3];
            #pragma unroll
            for (int i = 0; i < 8; i++) {
                asm("fma.rn.f32x2 %0, %1, %2, %0;" : "+l"(acc[i][0]) : "l"(aa[i]), "l"(b0));
                asm("fma.rn.f32x2 %0, %1, %2, %0;" : "+l"(acc[i][1]) : "l"(aa[i]), "l"(b1));
                asm("fma.rn.f32x2 %0, %1, %2, %0;" : "+l"(acc[i][2]) : "l"(aa[i]), "l"(b2));
                asm("fma.rn.f32x2 %0, %1, %2, %0;" : "+l"(acc[i][3]) : "l"(aa[i]), "l"(b3));
            }
        }
        __syncthreads();
    }

    // store C
    #pragma unroll
    for (int i = 0; i < 8; i++) {
        int gr = rowBase + ty * 8 + i;
        if (gr >= M) continue;
        unsigned long long* crow =
            reinterpret_cast<unsigned long long*>(C + (size_t)gr * 128 + tx * 8);
        crow[0] = acc[i][0]; crow[1] = acc[i][1];
        crow[2] = acc[i][2]; crow[3] = acc[i][3];
    }

    // fused attention dot-products: a_src[row][h], a_dst[row][h]
    float asv[8], adv[8];
    #pragma unroll
    for (int j = 0; j < 8; j++) {
        asv[j] = att_src[tx * 8 + j];
        adv[j] = att_dst[tx * 8 + j];
    }
    float* sredS = &As[0][0];   // [128][16]
    float* sredD = &Bs[0][0];
    #pragma unroll
    for (int i = 0; i < 8; i++) {
        float ps = 0.f, pd = 0.f;
        #pragma unroll
        for (int j = 0; j < 4; j++) {
            float2 c = unpack2(acc[i][j]);
            ps += c.x * asv[2 * j] + c.y * asv[2 * j + 1];
            pd += c.x * adv[2 * j] + c.y * adv[2 * j + 1];
        }
        int row = ty * 8 + i;
        sredS[row * 16 + tx] = ps;
        sredD[row * 16 + tx] = pd;
    }
    __syncthreads();
    {
        int row  = t >> 1;
        int half = t & 1;
        int gr = rowBase + row;
        if (gr < M) {
            float ss = 0.f, sd = 0.f;
            #pragma unroll
            for (int k = 0; k < 8; k++) {
                ss += sredS[row * 16 + half * 8 + k];
                sd += sredD[row * 16 + half * 8 + k];
            }
            g_asrc[gr * 2 + half] = ss;
            g_adst[gr * 2 + half] = sd;
        }
    }
}

// ---------------- generic SGEMM (40-col head) --------------------------------
#define BM 64
#define BN 64
#define BK 16
__global__ void k_sgemm(const float* __restrict__ A, const float* __restrict__ B,
                        float* __restrict__ C, int M, int Nc, int K) {
    __shared__ __align__(16) float As[BK][BM];
    __shared__ __align__(16) float Bs[BK][BN];
    int t  = threadIdx.x;
    int tx = t & 15, ty = t >> 4;
    int rowBase = blockIdx.y * BM;
    int colBase = blockIdx.x * BN;

    float acc[4][4] = {};
    int aRow = t >> 2;
    int aK4  = (t & 3) * 4;
    int bK   = t >> 4;
    int bC4  = (t & 15) * 4;

    for (int k0 = 0; k0 < K; k0 += BK) {
        float4 av = make_float4(0.f, 0.f, 0.f, 0.f);
        int gr = rowBase + aRow;
        if (gr < M) av = *reinterpret_cast<const float4*>(A + (size_t)gr * K + k0 + aK4);
        As[aK4 + 0][aRow] = av.x; As[aK4 + 1][aRow] = av.y;
        As[aK4 + 2][aRow] = av.z; As[aK4 + 3][aRow] = av.w;

        float4 bv = make_float4(0.f, 0.f, 0.f, 0.f);
        int gc = colBase + bC4;
        const float* brow = B + (size_t)(k0 + bK) * Nc;
        if (gc + 3 < Nc) bv = *reinterpret_cast<const float4*>(brow + gc);
        else {
            if (gc + 0 < Nc) bv.x = brow[gc + 0];
            if (gc + 1 < Nc) bv.y = brow[gc + 1];
            if (gc + 2 < Nc) bv.z = brow[gc + 2];
            if (gc + 3 < Nc) bv.w = brow[gc + 3];
        }
        *reinterpret_cast<float4*>(&Bs[bK][bC4]) = bv;
        __syncthreads();

        #pragma unroll
        for (int k = 0; k < BK; k++) {
            float4 a4 = *reinterpret_cast<const float4*>(&As[k][ty * 4]);
            float4 b4 = *reinterpret_cast<const float4*>(&Bs[k][tx * 4]);
            float a[4] = {a4.x, a4.y, a4.z, a4.w};
            float b[4] = {b4.x, b4.y, b4.z, b4.w};
            #pragma unroll
            for (int i = 0; i < 4; i++)
                #pragma unroll
                for (int j = 0; j < 4; j++)
                    acc[i][j] += a[i] * b[j];
        }
        __syncthreads();
    }

    #pragma unroll
    for (int i = 0; i < 4; i++) {
        int gr = rowBase + ty * 4 + i;
        if (gr >= M) continue;
        #pragma unroll
        for (int j = 0; j < 4; j++) {
            int gc = colBase + tx * 4 + j;
            if (gc < Nc) C[(size_t)gr * Nc + gc] = acc[i][j];
        }
    }
}

// ------- fused segment-softmax + weighted aggregate + epilogue (per warp) ----
template <bool FIRST>
__global__ void k_gat(const float* __restrict__ bias,
                      const float* __restrict__ gamma, const float* __restrict__ beta,
                      const float* __restrict__ mean,  const float* __restrict__ var) {
    int gt = blockIdx.x * blockDim.x + threadIdx.x;
    int w = gt >> 5, lane = gt & 31;
    if (w >= NNODES) return;
    int beg = g_rowptr[w], end = g_rowptr[w + 1];
    float ad0 = g_adst[w * 2], ad1 = g_adst[w * 2 + 1];

    // pass 1: online (max, sum) per head, lane-strided
    float m0 = -3.0e38f, d0 = 0.f, m1 = -3.0e38f, d1 = 0.f;
    for (int p = beg + lane; p < end; p += 32) {
        int s = g_csr_src[p];
        float e0 = g_asrc[s * 2]     + ad0;
        float e1 = g_asrc[s * 2 + 1] + ad1;
        e0 = e0 > 0.f ? e0 : NEG_SLOPE * e0;
        e1 = e1 > 0.f ? e1 : NEG_SLOPE * e1;
        float nm0 = fmaxf(m0, e0);
        d0 = d0 * expf(m0 - nm0) + expf(e0 - nm0); m0 = nm0;
        float nm1 = fmaxf(m1, e1);
        d1 = d1 * expf(m1 - nm1) + expf(e1 - nm1); m1 = nm1;
    }
    #pragma unroll
    for (int o = 16; o; o >>= 1) {
        float mo = __shfl_xor_sync(FULLM, m0, o);
        float dd = __shfl_xor_sync(FULLM, d0, o);
        float nm = fmaxf(m0, mo);
        d0 = d0 * expf(m0 - nm) + dd * expf(mo - nm); m0 = nm;
        mo = __shfl_xor_sync(FULLM, m1, o);
        dd = __shfl_xor_sync(FULLM, d1, o);
        nm = fmaxf(m1, mo);
        d1 = d1 * expf(m1 - nm) + dd * expf(mo - nm); m1 = nm;
    }
    float inv0 = 1.f / (d0 + 1e-16f);
    float inv1 = 1.f / (d1 + 1e-16f);

    // pass 2: per 32-edge chunk compute alpha (lane-strided), broadcast, gather h
    float4 acc = make_float4(0.f, 0.f, 0.f, 0.f);
    for (int base = beg; base < end; base += 32) {
        int p = base + lane;
        int   sreg = 0;
        float a0r = 0.f, a1r = 0.f;
        if (p < end) {
            sreg = g_csr_src[p];
            float e0 = g_asrc[sreg * 2]     + ad0;
            float e1 = g_asrc[sreg * 2 + 1] + ad1;
            e0 = e0 > 0.f ? e0 : NEG_SLOPE * e0;
            e1 = e1 > 0.f ? e1 : NEG_SLOPE * e1;
            a0r = expf(e0 - m0) * inv0;
            a1r = expf(e1 - m1) * inv1;
        }
        int cnt = min(32, end - base);
        #pragma unroll 4
        for (int k = 0; k < cnt; k++) {
            int   s  = __shfl_sync(FULLM, sreg, k);
            float a0 = __shfl_sync(FULLM, a0r,  k);
            float a1 = __shfl_sync(FULLM, a1r,  k);
            float a  = (lane < 16) ? a0 : a1;
            float4 v = *reinterpret_cast<const float4*>(g_h + (size_t)s * HC + lane * 4);
            acc.x += a * v.x; acc.y += a * v.y;
            acc.z += a * v.z; acc.w += a * v.w;
        }
    }

    int j = lane * 4;
    float4 b = *reinterpret_cast<const float4*>(bias + j);
    float4 r = make_float4(acc.x + b.x, acc.y + b.y, acc.z + b.z, acc.w + b.w);
    if (FIRST) {
        float4 gm = *reinterpret_cast<const float4*>(gamma + j);
        float4 bt = *reinterpret_cast<const float4*>(beta + j);
        float4 mn = *reinterpret_cast<const float4*>(mean + j);
        float4 vr = *reinterpret_cast<const float4*>(var + j);
        r.x = (r.x - mn.x) * rsqrtf(vr.x + BN_EPS) * gm.x + bt.x;
        r.y = (r.y - mn.y) * rsqrtf(vr.y + BN_EPS) * gm.y + bt.y;
        r.z = (r.z - mn.z) * rsqrtf(vr.z + BN_EPS) * gm.z + bt.z;
        r.w = (r.w - mn.w) * rsqrtf(vr.w + BN_EPS) * gm.w + bt.w;
        r.x = r.x > 0.f ? r.x : expm1f(r.x);
        r.y = r.y > 0.f ? r.y : expm1f(r.y);
        r.z = r.z > 0.f ? r.z : expm1f(r.z);
        r.w = r.w > 0.f ? r.w : expm1f(r.w);
        *reinterpret_cast<float4*>(g_x1 + (size_t)w * HC + j) = r;
    } else {
        float4 p1 = *reinterpret_cast<const float4*>(g_x1 + (size_t)w * HC + j);
        r.x = fmaxf(r.x, p1.x); r.y = fmaxf(r.y, p1.y);
        r.z = fmaxf(r.z, p1.z); r.w = fmaxf(r.w, p1.w);        // JK 'max'
        *reinterpret_cast<float4*>(g_x2 + (size_t)w * HC + j) = r;
    }
}

// ---------------- bias + row log-softmax -------------------------------------
__global__ void k_lsm(const float* __restrict__ bf, float* __restrict__ out) {
    int gt = blockIdx.x * blockDim.x + threadIdx.x;
    int w = gt >> 5, lane = gt & 31;
    if (w >= NNODES) return;
    const float* row = g_logits + (size_t)w * NOUTC;
    float l0 = row[lane] + bf[lane];
    float l1 = (lane < 8) ? (row[32 + lane] + bf[32 + lane]) : -3.0e38f;
    float m = fmaxf(l0, l1);
    for (int o = 16; o; o >>= 1) m = fmaxf(m, __shfl_xor_sync(FULLM, m, o));
    float s = expf(l0 - m) + ((lane < 8) ? expf(l1 - m) : 0.f);
    for (int o = 16; o; o >>= 1) s += __shfl_xor_sync(FULLM, s, o);
    float lse = m + logf(s);
    out[(size_t)w * NOUTC + lane] = l0 - lse;
    if (lane < 8) out[(size_t)w * NOUTC + 32 + lane] = l1 - lse;
}

// ---------------- launch -----------------------------------------------------
extern "C" void kernel_launch(void* const* d_in, const int* in_sizes, int n_in,
                              void* d_out, int out_size) {
    const float* x     = (const float*)d_in[0];
    const void*  ei    = d_in[1];
    const float* W1    = (const float*)d_in[2];
    const float* as1   = (const float*)d_in[3];
    const float* ad1   = (const float*)d_in[4];
    const float* b1    = (const float*)d_in[5];
    const float* gamma = (const float*)d_in[6];
    const float* beta  = (const float*)d_in[7];
    const float* mean  = (const float*)d_in[8];
    const float* var   = (const float*)d_in[9];
    const float* W2    = (const float*)d_in[10];
    const float* as2   = (const float*)d_in[11];
    const float* ad2   = (const float*)d_in[12];
    const float* b2    = (const float*)d_in[13];
    const float* Wf    = (const float*)d_in[14];
    const float* bf    = (const float*)d_in[15];
    float* out = (float*)d_out;

    float *hP, *x1P, *x2P, *lgP;
    cudaGetSymbolAddress((void**)&hP,  g_h);
    cudaGetSymbolAddress((void**)&x1P, g_x1);
    cudaGetSymbolAddress((void**)&x2P, g_x2);
    cudaGetSymbolAddress((void**)&lgP, g_logits);

    const int WPN = (NNODES * 32 + 255) / 256;   // warp-per-node grids

    k_detect<<<1, 32>>>((const int*)ei);
    k_zero<<<(NNODES + 255) / 256, 256>>>();
    k_count<<<(ETOT + 255) / 256, 256>>>(ei);
    k_scan1<<<NSCANB, 1024>>>();
    k_scan2<<<1, 32>>>();
    k_scan3<<<(NNODES + 255) / 256, 256>>>();
    k_fill<<<(ETOT + 255) / 256, 256>>>(ei);

    dim3 gemmG((NNODES + 127) / 128);
    dim3 g40((NOUTC + BN - 1) / BN, (NNODES + BM - 1) / BM);

    // layer 1
    k_sgemm128<<<gemmG, 256>>>(x, W1, hP, NNODES, as1, ad1);
    k_gat<true><<<WPN, 256>>>(b1, gamma, beta, mean, var);

    // layer 2
    k_sgemm128<<<gemmG, 256>>>(x1P, W2, hP, NNODES, as2, ad2);
    k_gat<false><<<WPN, 256>>>(b2, nullptr, nullptr, nullptr, nullptr);

    // head
    k_sgemm<<<g40, 256>>>(x2P, Wf, lgP, NNODES, NOUTC, HC);
    k_lsm<<<WPN, 256>>>(bf, out);
}

// round 6
// speedup vs baseline: 1.1246x; 1.1246x over previous
#include <cuda_runtime.h>
#include <math.h>

#define NNODES 50000
#define NEDGES 800000
#define ETOT   (NEDGES + NNODES)
#define HC     128
#define NOUTC  40
#define NEG_SLOPE 0.2f
#define BN_EPS 1e-5f
#define NSCANB ((NNODES + 1023) / 1024)
#define FULLM 0xffffffffu

// ---------------- scratch (static device arrays; no runtime alloc) ----------
static __device__ __align__(16) float g_h[NNODES * HC];
static __device__ __align__(16) float g_x1[NNODES * HC];
static __device__ __align__(16) float g_x2[NNODES * HC];
static __device__ float g_asrc[NNODES * 2];
static __device__ float g_adst[NNODES * 2];
static __device__ __align__(16) float g_e[ETOT * 2];   // e then alpha (CSR order)
static __device__ int   g_deg[NNODES];
static __device__ int   g_rowptr[NNODES + 1];
static __device__ int   g_bsum[NSCANB + 1];
static __device__ int   g_tick[ETOT];
static __device__ int   g_csr_src[ETOT];
static __device__ int   g_is64;

// ---------------- init: zero degrees + edge dtype detect ---------------------
__global__ void k_init(const int* ei32) {
    int i = blockIdx.x * blockDim.x + threadIdx.x;
    if (i < NNODES) g_deg[i] = 0;
    if (i == 0) {
        int any = 0;
        #pragma unroll 1
        for (int k = 0; k < 256; k++) any |= ei32[2 * k + 1];
        g_is64 = (any == 0) ? 1 : 0;   // int64 ids < 50000 -> high words all 0
    }
}

__device__ __forceinline__ int edge_idx(const void* ei, int pos) {
    if (g_is64) return (int)((const long long*)ei)[pos];
    return ((const int*)ei)[pos];
}

// ---------------- CSR build --------------------------------------------------
__global__ void k_count(const void* ei) {
    int i = blockIdx.x * blockDim.x + threadIdx.x;
    if (i >= ETOT) return;
    int d = (i < NEDGES) ? edge_idx(ei, NEDGES + i) : (i - NEDGES);
    g_tick[i] = atomicAdd(&g_deg[d], 1);
}

__global__ void k_scan1() {
    __shared__ int s[1024];
    int t = threadIdx.x;
    int idx = blockIdx.x * 1024 + t;
    int v = (idx < NNODES) ? g_deg[idx] : 0;
    s[t] = v;
    __syncthreads();
    #pragma unroll
    for (int o = 1; o < 1024; o <<= 1) {
        int add = (t >= o) ? s[t - o] : 0;
        __syncthreads();
        s[t] += add;
        __syncthreads();
    }
    if (idx < NNODES) g_rowptr[idx + 1] = s[t];
    if (t == 1023) g_bsum[blockIdx.x] = s[1023];
    if (idx == 0) g_rowptr[0] = 0;
}

// merged block-sum prefix + offset add (warp-parallel prefix per block)
__global__ void k_scan3() {
    __shared__ int pre;
    int b = blockIdx.x;
    if (threadIdx.x < 32) {
        int v = 0;
        if (threadIdx.x < b) v = g_bsum[threadIdx.x];
        if (threadIdx.x + 32 < b) v += g_bsum[threadIdx.x + 32];
        #pragma unroll
        for (int o = 16; o; o >>= 1) v += __shfl_xor_sync(FULLM, v, o);
        if (threadIdx.x == 0) pre = v;
    }
    __syncthreads();
    int idx = b * 1024 + threadIdx.x;
    if (idx < NNODES) g_rowptr[idx + 1] += pre;
}

__global__ void k_fill(const void* ei) {
    int i = blockIdx.x * blockDim.x + threadIdx.x;
    if (i >= ETOT) return;
    int s, d;
    if (i < NEDGES) { s = edge_idx(ei, i); d = edge_idx(ei, NEDGES + i); }
    else            { s = d = i - NEDGES; }
    g_csr_src[g_rowptr[d] + g_tick[i]] = s;   // atomic-free (ticket)
}

// ---------------- packed-f32x2 SGEMM (K=Nc=128) + fused attention dots -------
__device__ __forceinline__ unsigned long long pack2(float a) {
    unsigned long long r;
    unsigned int u = __float_as_uint(a);
    asm("mov.b64 %0, {%1, %1};" : "=l"(r) : "r"(u));
    return r;
}
__device__ __forceinline__ float2 unpack2(unsigned long long v) {
    float2 f;
    asm("mov.b64 {%0, %1}, %2;" : "=f"(f.x), "=f"(f.y) : "l"(v));
    return f;
}

__global__ __launch_bounds__(256, 2)
void k_sgemm128(const float* __restrict__ A, const float* __restrict__ B,
                float* __restrict__ C, int M,
                const float* __restrict__ att_src, const float* __restrict__ att_dst) {
    __shared__ __align__(16) float As[16][128];   // transposed A tile
    __shared__ __align__(16) float Bs[16][128];
    int t  = threadIdx.x;
    int tx = t & 15, ty = t >> 4;
    int rowBase = blockIdx.x * 128;

    unsigned long long acc[8][4];
    #pragma unroll
    for (int i = 0; i < 8; i++)
        #pragma unroll
        for (int j = 0; j < 4; j++) acc[i][j] = 0ull;

    int aRow = t >> 1;          // 0..127
    int aK   = (t & 1) * 8;     // 0 or 8
    int bRow = t >> 4;          // 0..15
    int bC   = (t & 15) * 8;    // 0..120

    for (int k0 = 0; k0 < 128; k0 += 16) {
        float4 av0 = make_float4(0.f, 0.f, 0.f, 0.f), av1 = av0;
        int gr = rowBase + aRow;
        if (gr < M) {
            const float* ap = A + (size_t)gr * 128 + k0 + aK;
            av0 = *reinterpret_cast<const float4*>(ap);
            av1 = *reinterpret_cast<const float4*>(ap + 4);
        }
        As[aK + 0][aRow] = av0.x; As[aK + 1][aRow] = av0.y;
        As[aK + 2][aRow] = av0.z; As[aK + 3][aRow] = av0.w;
        As[aK + 4][aRow] = av1.x; As[aK + 5][aRow] = av1.y;
        As[aK + 6][aRow] = av1.z; As[aK + 7][aRow] = av1.w;

        const float* bp = B + (size_t)(k0 + bRow) * 128 + bC;
        *reinterpret_cast<float4*>(&Bs[bRow][bC])     = *reinterpret_cast<const float4*>(bp);
        *reinterpret_cast<float4*>(&Bs[bRow][bC + 4]) = *reinterpret_cast<const float4*>(bp + 4);
        __syncthreads();

        #pragma unroll
        for (int k = 0; k < 16; k++) {
            float4 a0 = *reinterpret_cast<const float4*>(&As[k][ty * 8]);
            float4 a1 = *reinterpret_cast<const float4*>(&As[k][ty * 8 + 4]);
            unsigned long long aa[8];
            aa[0] = pack2(a0.x); aa[1] = pack2(a0.y); aa[2] = pack2(a0.z); aa[3] = pack2(a0.w);
            aa[4] = pack2(a1.x); aa[5] = pack2(a1.y); aa[6] = pack2(a1.z); aa[7] = pack2(a1.w);
            const unsigned long long* bpp =
                reinterpret_cast<const unsigned long long*>(&Bs[k][tx * 8]);
            unsigned long long b0 = bpp[0], b1 = bpp[1], b2 = bpp[2], b3 = bpp[3];
            #pragma unroll
            for (int i = 0; i < 8; i++) {
                asm("fma.rn.f32x2 %0, %1, %2, %0;" : "+l"(acc[i][0]) : "l"(aa[i]), "l"(b0));
                asm("fma.rn.f32x2 %0, %1, %2, %0;" : "+l"(acc[i][1]) : "l"(aa[i]), "l"(b1));
                asm("fma.rn.f32x2 %0, %1, %2, %0;" : "+l"(acc[i][2]) : "l"(aa[i]), "l"(b2));
                asm("fma.rn.f32x2 %0, %1, %2, %0;" : "+l"(acc[i][3]) : "l"(aa[i]), "l"(b3));
            }
        }
        __syncthreads();
    }

    // store C
    #pragma unroll
    for (int i = 0; i < 8; i++) {
        int gr = rowBase + ty * 8 + i;
        if (gr >= M) continue;
        unsigned long long* crow =
            reinterpret_cast<unsigned long long*>(C + (size_t)gr * 128 + tx * 8);
        crow[0] = acc[i][0]; crow[1] = acc[i][1];
        crow[2] = acc[i][2]; crow[3] = acc[i][3];
    }

    // fused attention dot-products
    float asv[8], adv[8];
    #pragma unroll
    for (int j = 0; j < 8; j++) {
        asv[j] = att_src[tx * 8 + j];
        adv[j] = att_dst[tx * 8 + j];
    }
    float* sredS = &As[0][0];   // [128][16]
    float* sredD = &Bs[0][0];
    #pragma unroll
    for (int i = 0; i < 8; i++) {
        float ps = 0.f, pd = 0.f;
        #pragma unroll
        for (int j = 0; j < 4; j++) {
            float2 c = unpack2(acc[i][j]);
            ps += c.x * asv[2 * j] + c.y * asv[2 * j + 1];
            pd += c.x * adv[2 * j] + c.y * adv[2 * j + 1];
        }
        int row = ty * 8 + i;
        sredS[row * 16 + tx] = ps;
        sredD[row * 16 + tx] = pd;
    }
    __syncthreads();
    {
        int row  = t >> 1;
        int half = t & 1;
        int gr = rowBase + row;
        if (gr < M) {
            float ss = 0.f, sd = 0.f;
            #pragma unroll
            for (int k = 0; k < 8; k++) {
                ss += sredS[row * 16 + half * 8 + k];
                sd += sredD[row * 16 + half * 8 + k];
            }
            g_asrc[gr * 2 + half] = ss;
            g_adst[gr * 2 + half] = sd;
        }
    }
}

// ------- fused softmax + aggregate, 3 sub-passes, materialized alpha ---------
template <bool FIRST>
__global__ __launch_bounds__(256)
void k_gat(const float* __restrict__ bias,
           const float* __restrict__ gamma, const float* __restrict__ beta,
           const float* __restrict__ mean,  const float* __restrict__ var) {
    int gt = blockIdx.x * blockDim.x + threadIdx.x;
    int w = gt >> 5, lane = gt & 31;
    if (w >= NNODES) return;
    int beg = g_rowptr[w], end = g_rowptr[w + 1];
    float ad0 = g_adst[w * 2], ad1 = g_adst[w * 2 + 1];

    // pass 1: compute e, store; online (max,sum) per head, lane-strided
    float m0 = -3.0e38f, d0 = 0.f, m1 = -3.0e38f, d1 = 0.f;
    for (int p = beg + lane; p < end; p += 32) {
        int s = g_csr_src[p];
        float e0 = g_asrc[s * 2]     + ad0;
        float e1 = g_asrc[s * 2 + 1] + ad1;
        e0 = e0 > 0.f ? e0 : NEG_SLOPE * e0;
        e1 = e1 > 0.f ? e1 : NEG_SLOPE * e1;
        float2 ev; ev.x = e0; ev.y = e1;
        *reinterpret_cast<float2*>(g_e + 2 * p) = ev;
        float nm0 = fmaxf(m0, e0);
        d0 = d0 * expf(m0 - nm0) + expf(e0 - nm0); m0 = nm0;
        float nm1 = fmaxf(m1, e1);
        d1 = d1 * expf(m1 - nm1) + expf(e1 - nm1); m1 = nm1;
    }
    #pragma unroll
    for (int o = 16; o; o >>= 1) {
        float mo = __shfl_xor_sync(FULLM, m0, o);
        float dd = __shfl_xor_sync(FULLM, d0, o);
        float nm = fmaxf(m0, mo);
        d0 = d0 * expf(m0 - nm) + dd * expf(mo - nm); m0 = nm;
        mo = __shfl_xor_sync(FULLM, m1, o);
        dd = __shfl_xor_sync(FULLM, d1, o);
        nm = fmaxf(m1, mo);
        d1 = d1 * expf(m1 - nm) + dd * expf(mo - nm); m1 = nm;
    }
    float inv0 = 1.f / (d0 + 1e-16f);
    float inv1 = 1.f / (d1 + 1e-16f);

    // pass 2: alpha in place, lane-strided
    for (int p = beg + lane; p < end; p += 32) {
        float2 ev = *reinterpret_cast<const float2*>(g_e + 2 * p);
        ev.x = expf(ev.x - m0) * inv0;
        ev.y = expf(ev.y - m1) * inv1;
        *reinterpret_cast<float2*>(g_e + 2 * p) = ev;
    }
    __syncwarp();

    // pass 3: gather with broadcast alpha, dual accumulators for MLP
    float4 acc0 = make_float4(0.f, 0.f, 0.f, 0.f);
    float4 acc1 = make_float4(0.f, 0.f, 0.f, 0.f);
    int p = beg;
    for (; p + 1 < end; p += 2) {
        int s0 = g_csr_src[p];
        int s1 = g_csr_src[p + 1];
        float2 e0 = *reinterpret_cast<const float2*>(g_e + 2 * p);
        float2 e1 = *reinterpret_cast<const float2*>(g_e + 2 * (p + 1));
        float a0 = (lane < 16) ? e0.x : e0.y;
        float a1 = (lane < 16) ? e1.x : e1.y;
        float4 v0 = *reinterpret_cast<const float4*>(g_h + (size_t)s0 * HC + lane * 4);
        float4 v1 = *reinterpret_cast<const float4*>(g_h + (size_t)s1 * HC + lane * 4);
        acc0.x += a0 * v0.x; acc0.y += a0 * v0.y;
        acc0.z += a0 * v0.z; acc0.w += a0 * v0.w;
        acc1.x += a1 * v1.x; acc1.y += a1 * v1.y;
        acc1.z += a1 * v1.z; acc1.w += a1 * v1.w;
    }
    if (p < end) {
        int s0 = g_csr_src[p];
        float2 e0 = *reinterpret_cast<const float2*>(g_e + 2 * p);
        float a0 = (lane < 16) ? e0.x : e0.y;
        float4 v0 = *reinterpret_cast<const float4*>(g_h + (size_t)s0 * HC + lane * 4);
        acc0.x += a0 * v0.x; acc0.y += a0 * v0.y;
        acc0.z += a0 * v0.z; acc0.w += a0 * v0.w;
    }
    float4 acc = make_float4(acc0.x + acc1.x, acc0.y + acc1.y,
                             acc0.z + acc1.z, acc0.w + acc1.w);

    int j = lane * 4;
    float4 b = *reinterpret_cast<const float4*>(bias + j);
    float4 r = make_float4(acc.x + b.x, acc.y + b.y, acc.z + b.z, acc.w + b.w);
    if (FIRST) {
        float4 gm = *reinterpret_cast<const float4*>(gamma + j);
        float4 bt = *reinterpret_cast<const float4*>(beta + j);
        float4 mn = *reinterpret_cast<const float4*>(mean + j);
        float4 vr = *reinterpret_cast<const float4*>(var + j);
        r.x = (r.x - mn.x) * rsqrtf(vr.x + BN_EPS) * gm.x + bt.x;
        r.y = (r.y - mn.y) * rsqrtf(vr.y + BN_EPS) * gm.y + bt.y;
        r.z = (r.z - mn.z) * rsqrtf(vr.z + BN_EPS) * gm.z + bt.z;
        r.w = (r.w - mn.w) * rsqrtf(vr.w + BN_EPS) * gm.w + bt.w;
        r.x = r.x > 0.f ? r.x : expm1f(r.x);
        r.y = r.y > 0.f ? r.y : expm1f(r.y);
        r.z = r.z > 0.f ? r.z : expm1f(r.z);
        r.w = r.w > 0.f ? r.w : expm1f(r.w);
        *reinterpret_cast<float4*>(g_x1 + (size_t)w * HC + j) = r;
    } else {
        float4 p1 = *reinterpret_cast<const float4*>(g_x1 + (size_t)w * HC + j);
        r.x = fmaxf(r.x, p1.x); r.y = fmaxf(r.y, p1.y);
        r.z = fmaxf(r.z, p1.z); r.w = fmaxf(r.w, p1.w);        // JK 'max'
        *reinterpret_cast<float4*>(g_x2 + (size_t)w * HC + j) = r;
    }
}

// ------- head GEMM (M=64/block, Nc=40, K=128) + fused bias + log-softmax -----
__global__ __launch_bounds__(256)
void k_head(const float* __restrict__ A, const float* __restrict__ B,
            const float* __restrict__ bf, float* __restrict__ out, int M) {
    __shared__ __align__(16) float As[16][64];
    __shared__ __align__(16) float Bs[16][64];
    __shared__ float sred[64][17];
    __shared__ float srow[64];
    int t  = threadIdx.x;
    int tx = t & 15, ty = t >> 4;
    int rowBase = blockIdx.x * 64;

    float acc[4][4] = {};
    int aRow = t >> 2;
    int aK4  = (t & 3) * 4;
    int bK   = t >> 4;
    int bC4  = (t & 15) * 4;

    for (int k0 = 0; k0 < 128; k0 += 16) {
        float4 av = make_float4(0.f, 0.f, 0.f, 0.f);
        int gr = rowBase + aRow;
        if (gr < M) av = *reinterpret_cast<const float4*>(A + (size_t)gr * 128 + k0 + aK4);
        As[aK4 + 0][aRow] = av.x; As[aK4 + 1][aRow] = av.y;
        As[aK4 + 2][aRow] = av.z; As[aK4 + 3][aRow] = av.w;

        float4 bv = make_float4(0.f, 0.f, 0.f, 0.f);
        const float* brow = B + (size_t)(k0 + bK) * NOUTC;
        if (bC4 + 0 < NOUTC) bv.x = brow[bC4 + 0];
        if (bC4 + 1 < NOUTC) bv.y = brow[bC4 + 1];
        if (bC4 + 2 < NOUTC) bv.z = brow[bC4 + 2];
        if (bC4 + 3 < NOUTC) bv.w = brow[bC4 + 3];
        *reinterpret_cast<float4*>(&Bs[bK][bC4]) = bv;
        __syncthreads();

        #pragma unroll
        for (int k = 0; k < 16; k++) {
            float4 a4 = *reinterpret_cast<const float4*>(&As[k][ty * 4]);
            float4 b4 = *reinterpret_cast<const float4*>(&Bs[k][tx * 4]);
            float a[4] = {a4.x, a4.y, a4.z, a4.w};
            float b[4] = {b4.x, b4.y, b4.z, b4.w};
            #pragma unroll
            for (int i = 0; i < 4; i++)
                #pragma unroll
                for (int j = 0; j < 4; j++)
                    acc[i][j] += a[i] * b[j];
        }
        __syncthreads();
    }

    // add bias -> logits (cols tx*4+j, valid < 40)
    float bfv[4];
    #pragma unroll
    for (int j = 0; j < 4; j++)
        bfv[j] = (tx * 4 + j < NOUTC) ? bf[tx * 4 + j] : 0.f;
    #pragma unroll
    for (int i = 0; i < 4; i++)
        #pragma unroll
        for (int j = 0; j < 4; j++)
            acc[i][j] += bfv[j];

    // row max partials
    #pragma unroll
    for (int i = 0; i < 4; i++) {
        float pm = -3.0e38f;
        #pragma unroll
        for (int j = 0; j < 4; j++)
            if (tx * 4 + j < NOUTC) pm = fmaxf(pm, acc[i][j]);
        sred[ty * 4 + i][tx] = pm;
    }
    __syncthreads();
    if (t < 64) {
        float m = -3.0e38f;
        #pragma unroll
        for (int k = 0; k < 10; k++) m = fmaxf(m, sred[t][k]);
        srow[t] = m;
    }
    __syncthreads();
    // row sum partials
    #pragma unroll
    for (int i = 0; i < 4; i++) {
        float m = srow[ty * 4 + i];
        float ps = 0.f;
        #pragma unroll
        for (int j = 0; j < 4; j++)
            if (tx * 4 + j < NOUTC) ps += expf(acc[i][j] - m);
        sred[ty * 4 + i][tx] = ps;
    }
    __syncthreads();
    if (t < 64) {
        float s = 0.f;
        #pragma unroll
        for (int k = 0; k < 10; k++) s += sred[t][k];
        srow[t] += logf(s);           // lse
    }
    __syncthreads();

    #pragma unroll
    for (int i = 0; i < 4; i++) {
        int gr = rowBase + ty * 4 + i;
        if (gr >= M) continue;
        float lse = srow[ty * 4 + i];
        #pragma unroll
        for (int j = 0; j < 4; j++) {
            int gc = tx * 4 + j;
            if (gc < NOUTC) out[(size_t)gr * NOUTC + gc] = acc[i][j] - lse;
        }
    }
}

// ---------------- launch -----------------------------------------------------
extern "C" void kernel_launch(void* const* d_in, const int* in_sizes, int n_in,
                              void* d_out, int out_size) {
    const float* x     = (const float*)d_in[0];
    const void*  ei    = d_in[1];
    const float* W1    = (const float*)d_in[2];
    const float* as1   = (const float*)d_in[3];
    const float* ad1   = (const float*)d_in[4];
    const float* b1    = (const float*)d_in[5];
    const float* gamma = (const float*)d_in[6];
    const float* beta  = (const float*)d_in[7];
    const float* mean  = (const float*)d_in[8];
    const float* var   = (const float*)d_in[9];
    const float* W2    = (const float*)d_in[10];
    const float* as2   = (const float*)d_in[11];
    const float* ad2   = (const float*)d_in[12];
    const float* b2    = (const float*)d_in[13];
    const float* Wf    = (const float*)d_in[14];
    const float* bf    = (const float*)d_in[15];
    float* out = (float*)d_out;

    float *hP, *x1P, *x2P;
    cudaGetSymbolAddress((void**)&hP,  g_h);
    cudaGetSymbolAddress((void**)&x1P, g_x1);
    cudaGetSymbolAddress((void**)&x2P, g_x2);

    const int WPN = (NNODES * 32 + 255) / 256;   // warp-per-node grids

    k_init<<<(NNODES + 255) / 256, 256>>>((const int*)ei);
    k_count<<<(ETOT + 255) / 256, 256>>>(ei);
    k_scan1<<<NSCANB, 1024>>>();
    k_scan3<<<NSCANB, 1024>>>();
    k_fill<<<(ETOT + 255) / 256, 256>>>(ei);

    dim3 gemmG((NNODES + 127) / 128);

    // layer 1
    k_sgemm128<<<gemmG, 256>>>(x, W1, hP, NNODES, as1, ad1);
    k_gat<true><<<WPN, 256>>>(b1, gamma, beta, mean, var);

    // layer 2
    k_sgemm128<<<gemmG, 256>>>(x1P, W2, hP, NNODES, as2, ad2);
    k_gat<false><<<WPN, 256>>>(b2, nullptr, nullptr, nullptr, nullptr);

    // head: GEMM + bias + log-softmax fused
    k_head<<<(NNODES + 63) / 64, 256>>>(x2P, Wf, bf, out, NNODES);
}

// round 9
// speedup vs baseline: 1.2512x; 1.1126x over previous
#include <cuda_runtime.h>
#include <cuda_fp16.h>
#include <math.h>

#define NNODES 50000
#define NEDGES 800000
#define ETOT   (NEDGES + NNODES)
#define HC     128
#define NOUTC  40
#define NEG_SLOPE 0.2f
#define BN_EPS 1e-5f
#define NSCANB ((NNODES + 1023) / 1024)
#define FULLM 0xffffffffu

// ---------------- scratch (static device arrays; no runtime alloc) ----------
static __device__ __align__(16) __half g_hh[NNODES * HC];   // h in fp16 (gather)
static __device__ __align__(16) float g_x1[NNODES * HC];
static __device__ __align__(16) float g_x2[NNODES * HC];
static __device__ float g_asrc[NNODES * 2];
static __device__ float g_adst[NNODES * 2];
static __device__ __align__(16) float g_e[ETOT * 2];   // e then alpha (CSR order)
static __device__ int   g_deg[NNODES];
static __device__ int   g_rowptr[NNODES + 1];
static __device__ int   g_bsum[NSCANB + 1];
static __device__ int   g_tick[ETOT];
static __device__ int   g_csr_src[ETOT];
static __device__ int   g_is64;

// ---------------- half2 <-> u32 bit casts (no named intrinsic exists) -------
__device__ __forceinline__ unsigned int h2_to_u32(__half2 h) {
    return *reinterpret_cast<unsigned int*>(&h);
}
__device__ __forceinline__ __half2 u32_to_h2(unsigned int u) {
    return *reinterpret_cast<__half2*>(&u);
}

// ---------------- init: zero degrees + edge dtype detect ---------------------
__global__ void k_init(const int* ei32) {
    int i = blockIdx.x * blockDim.x + threadIdx.x;
    if (i < NNODES) g_deg[i] = 0;
    if (i == 0) {
        int any = 0;
        #pragma unroll 1
        for (int k = 0; k < 256; k++) any |= ei32[2 * k + 1];
        g_is64 = (any == 0) ? 1 : 0;   // int64 ids < 50000 -> high words all 0
    }
}

__device__ __forceinline__ int edge_idx(const void* ei, int pos) {
    if (g_is64) return (int)((const long long*)ei)[pos];
    return ((const int*)ei)[pos];
}

// ---------------- CSR build --------------------------------------------------
__global__ void k_count(const void* ei) {
    int i = blockIdx.x * blockDim.x + threadIdx.x;
    if (i >= ETOT) return;
    int d = (i < NEDGES) ? edge_idx(ei, NEDGES + i) : (i - NEDGES);
    g_tick[i] = atomicAdd(&g_deg[d], 1);
}

__global__ void k_scan1() {
    __shared__ int s[1024];
    int t = threadIdx.x;
    int idx = blockIdx.x * 1024 + t;
    int v = (idx < NNODES) ? g_deg[idx] : 0;
    s[t] = v;
    __syncthreads();
    #pragma unroll
    for (int o = 1; o < 1024; o <<= 1) {
        int add = (t >= o) ? s[t - o] : 0;
        __syncthreads();
        s[t] += add;
        __syncthreads();
    }
    if (idx < NNODES) g_rowptr[idx + 1] = s[t];
    if (t == 1023) g_bsum[blockIdx.x] = s[1023];
    if (idx == 0) g_rowptr[0] = 0;
}

// merged block-sum prefix + offset add (warp-parallel prefix per block)
__global__ void k_scan3() {
    __shared__ int pre;
    int b = blockIdx.x;
    if (threadIdx.x < 32) {
        int v = 0;
        if (threadIdx.x < b) v = g_bsum[threadIdx.x];
        if (threadIdx.x + 32 < b) v += g_bsum[threadIdx.x + 32];
        #pragma unroll
        for (int o = 16; o; o >>= 1) v += __shfl_xor_sync(FULLM, v, o);
        if (threadIdx.x == 0) pre = v;
    }
    __syncthreads();
    int idx = b * 1024 + threadIdx.x;
    if (idx < NNODES) g_rowptr[idx + 1] += pre;
}

__global__ void k_fill(const void* ei) {
    int i = blockIdx.x * blockDim.x + threadIdx.x;
    if (i >= ETOT) return;
    int s, d;
    if (i < NEDGES) { s = edge_idx(ei, i); d = edge_idx(ei, NEDGES + i); }
    else            { s = d = i - NEDGES; }
    g_csr_src[g_rowptr[d] + g_tick[i]] = s;   // atomic-free (ticket)
}

// ---------------- packed-f32x2 SGEMM (K=Nc=128), fp16 C, fused attn dots -----
__device__ __forceinline__ unsigned long long pack2(float a) {
    unsigned long long r;
    unsigned int u = __float_as_uint(a);
    asm("mov.b64 %0, {%1, %1};" : "=l"(r) : "r"(u));
    return r;
}
__device__ __forceinline__ float2 unpack2(unsigned long long v) {
    float2 f;
    asm("mov.b64 {%0, %1}, %2;" : "=f"(f.x), "=f"(f.y) : "l"(v));
    return f;
}

__global__ __launch_bounds__(256, 2)
void k_sgemm128(const float* __restrict__ A, const float* __restrict__ B,
                __half* __restrict__ C, int M,
                const float* __restrict__ att_src, const float* __restrict__ att_dst) {
    __shared__ __align__(16) float As[16][128];   // transposed A tile
    __shared__ __align__(16) float Bs[16][128];
    int t  = threadIdx.x;
    int tx = t & 15, ty = t >> 4;
    int rowBase = blockIdx.x * 128;

    unsigned long long acc[8][4];
    #pragma unroll
    for (int i = 0; i < 8; i++)
        #pragma unroll
        for (int j = 0; j < 4; j++) acc[i][j] = 0ull;

    int aRow = t >> 1;          // 0..127
    int aK   = (t & 1) * 8;     // 0 or 8
    int bRow = t >> 4;          // 0..15
    int bC   = (t & 15) * 8;    // 0..120

    for (int k0 = 0; k0 < 128; k0 += 16) {
        float4 av0 = make_float4(0.f, 0.f, 0.f, 0.f), av1 = av0;
        int gr = rowBase + aRow;
        if (gr < M) {
            const float* ap = A + (size_t)gr * 128 + k0 + aK;
            av0 = *reinterpret_cast<const float4*>(ap);
            av1 = *reinterpret_cast<const float4*>(ap + 4);
        }
        As[aK + 0][aRow] = av0.x; As[aK + 1][aRow] = av0.y;
        As[aK + 2][aRow] = av0.z; As[aK + 3][aRow] = av0.w;
        As[aK + 4][aRow] = av1.x; As[aK + 5][aRow] = av1.y;
        As[aK + 6][aRow] = av1.z; As[aK + 7][aRow] = av1.w;

        const float* bp = B + (size_t)(k0 + bRow) * 128 + bC;
        *reinterpret_cast<float4*>(&Bs[bRow][bC])     = *reinterpret_cast<const float4*>(bp);
        *reinterpret_cast<float4*>(&Bs[bRow][bC + 4]) = *reinterpret_cast<const float4*>(bp + 4);
        __syncthreads();

        #pragma unroll
        for (int k = 0; k < 16; k++) {
            float4 a0 = *reinterpret_cast<const float4*>(&As[k][ty * 8]);
            float4 a1 = *reinterpret_cast<const float4*>(&As[k][ty * 8 + 4]);
            unsigned long long aa[8];
            aa[0] = pack2(a0.x); aa[1] = pack2(a0.y); aa[2] = pack2(a0.z); aa[3] = pack2(a0.w);
            aa[4] = pack2(a1.x); aa[5] = pack2(a1.y); aa[6] = pack2(a1.z); aa[7] = pack2(a1.w);
            const unsigned long long* bpp =
                reinterpret_cast<const unsigned long long*>(&Bs[k][tx * 8]);
            unsigned long long b0 = bpp[0], b1 = bpp[1], b2 = bpp[2], b3 = bpp[3];
            #pragma unroll
            for (int i = 0; i < 8; i++) {
                asm("fma.rn.f32x2 %0, %1, %2, %0;" : "+l"(acc[i][0]) : "l"(aa[i]), "l"(b0));
                asm("fma.rn.f32x2 %0, %1, %2, %0;" : "+l"(acc[i][1]) : "l"(aa[i]), "l"(b1));
                asm("fma.rn.f32x2 %0, %1, %2, %0;" : "+l"(acc[i][2]) : "l"(aa[i]), "l"(b2));
                asm("fma.rn.f32x2 %0, %1, %2, %0;" : "+l"(acc[i][3]) : "l"(aa[i]), "l"(b3));
            }
        }
        __syncthreads();
    }

    // store C as fp16 (8 cols = 4 half2 = 16 B per thread-row)
    #pragma unroll
    for (int i = 0; i < 8; i++) {
        int gr = rowBase + ty * 8 + i;
        if (gr >= M) continue;
        uint4 pk;
        float2 c0 = unpack2(acc[i][0]);
        float2 c1 = unpack2(acc[i][1]);
        float2 c2 = unpack2(acc[i][2]);
        float2 c3 = unpack2(acc[i][3]);
        pk.x = h2_to_u32(__float22half2_rn(c0));
        pk.y = h2_to_u32(__float22half2_rn(c1));
        pk.z = h2_to_u32(__float22half2_rn(c2));
        pk.w = h2_to_u32(__float22half2_rn(c3));
        *reinterpret_cast<uint4*>(C + (size_t)gr * 128 + tx * 8) = pk;
    }

    // fused attention dot-products (fp32 accumulators)
    float asv[8], adv[8];
    #pragma unroll
    for (int j = 0; j < 8; j++) {
        asv[j] = att_src[tx * 8 + j];
        adv[j] = att_dst[tx * 8 + j];
    }
    float* sredS = &As[0][0];   // [128][16]
    float* sredD = &Bs[0][0];
    #pragma unroll
    for (int i = 0; i < 8; i++) {
        float ps = 0.f, pd = 0.f;
        #pragma unroll
        for (int j = 0; j < 4; j++) {
            float2 c = unpack2(acc[i][j]);
            ps += c.x * asv[2 * j] + c.y * asv[2 * j + 1];
            pd += c.x * adv[2 * j] + c.y * adv[2 * j + 1];
        }
        int row = ty * 8 + i;
        sredS[row * 16 + tx] = ps;
        sredD[row * 16 + tx] = pd;
    }
    __syncthreads();
    {
        int row  = t >> 1;
        int half = t & 1;
        int gr = rowBase + row;
        if (gr < M) {
            float ss = 0.f, sd = 0.f;
            #pragma unroll
            for (int k = 0; k < 8; k++) {
                ss += sredS[row * 16 + half * 8 + k];
                sd += sredD[row * 16 + half * 8 + k];
            }
            g_asrc[gr * 2 + half] = ss;
            g_adst[gr * 2 + half] = sd;
        }
    }
}

// ------- fused softmax + aggregate (fp16 gather), materialized alpha ---------
template <bool FIRST>
__global__ __launch_bounds__(256)
void k_gat(const float* __restrict__ bias,
           const float* __restrict__ gamma, const float* __restrict__ beta,
           const float* __restrict__ mean,  const float* __restrict__ var) {
    int gt = blockIdx.x * blockDim.x + threadIdx.x;
    int w = gt >> 5, lane = gt & 31;
    if (w >= NNODES) return;
    int beg = g_rowptr[w], end = g_rowptr[w + 1];
    float ad0 = g_adst[w * 2], ad1 = g_adst[w * 2 + 1];

    // pass 1: compute e, store; online (max,sum) per head, lane-strided
    float m0 = -3.0e38f, d0 = 0.f, m1 = -3.0e38f, d1 = 0.f;
    for (int p = beg + lane; p < end; p += 32) {
        int s = g_csr_src[p];
        float e0 = g_asrc[s * 2]     + ad0;
        float e1 = g_asrc[s * 2 + 1] + ad1;
        e0 = e0 > 0.f ? e0 : NEG_SLOPE * e0;
        e1 = e1 > 0.f ? e1 : NEG_SLOPE * e1;
        float2 ev; ev.x = e0; ev.y = e1;
        *reinterpret_cast<float2*>(g_e + 2 * p) = ev;
        float nm0 = fmaxf(m0, e0);
        d0 = d0 * expf(m0 - nm0) + expf(e0 - nm0); m0 = nm0;
        float nm1 = fmaxf(m1, e1);
        d1 = d1 * expf(m1 - nm1) + expf(e1 - nm1); m1 = nm1;
    }
    #pragma unroll
    for (int o = 16; o; o >>= 1) {
        float mo = __shfl_xor_sync(FULLM, m0, o);
        float dd = __shfl_xor_sync(FULLM, d0, o);
        float nm = fmaxf(m0, mo);
        d0 = d0 * expf(m0 - nm) + dd * expf(mo - nm); m0 = nm;
        mo = __shfl_xor_sync(FULLM, m1, o);
        dd = __shfl_xor_sync(FULLM, d1, o);
        nm = fmaxf(m1, mo);
        d1 = d1 * expf(m1 - nm) + dd * expf(mo - nm); m1 = nm;
    }
    float inv0 = 1.f / (d0 + 1e-16f);
    float inv1 = 1.f / (d1 + 1e-16f);

    // pass 2: alpha in place, lane-strided
    for (int p = beg + lane; p < end; p += 32) {
        float2 ev = *reinterpret_cast<const float2*>(g_e + 2 * p);
        ev.x = expf(ev.x - m0) * inv0;
        ev.y = expf(ev.y - m1) * inv1;
        *reinterpret_cast<float2*>(g_e + 2 * p) = ev;
    }
    __syncwarp();

    // pass 3: fp16 gather with broadcast alpha, dual accumulators for MLP
    float4 acc0 = make_float4(0.f, 0.f, 0.f, 0.f);
    float4 acc1 = make_float4(0.f, 0.f, 0.f, 0.f);
    int p = beg;
    for (; p + 1 < end; p += 2) {
        int s0 = g_csr_src[p];
        int s1 = g_csr_src[p + 1];
        float2 e0 = *reinterpret_cast<const float2*>(g_e + 2 * p);
        float2 e1 = *reinterpret_cast<const float2*>(g_e + 2 * (p + 1));
        float a0 = (lane < 16) ? e0.x : e0.y;
        float a1 = (lane < 16) ? e1.x : e1.y;
        uint2 u0 = *reinterpret_cast<const uint2*>(g_hh + (size_t)s0 * HC + lane * 4);
        uint2 u1 = *reinterpret_cast<const uint2*>(g_hh + (size_t)s1 * HC + lane * 4);
        float2 v0a = __half22float2(u32_to_h2(u0.x));
        float2 v0b = __half22float2(u32_to_h2(u0.y));
        float2 v1a = __half22float2(u32_to_h2(u1.x));
        float2 v1b = __half22float2(u32_to_h2(u1.y));
        acc0.x += a0 * v0a.x; acc0.y += a0 * v0a.y;
        acc0.z += a0 * v0b.x; acc0.w += a0 * v0b.y;
        acc1.x += a1 * v1a.x; acc1.y += a1 * v1a.y;
        acc1.z += a1 * v1b.x; acc1.w += a1 * v1b.y;
    }
    if (p < end) {
        int s0 = g_csr_src[p];
        float2 e0 = *reinterpret_cast<const float2*>(g_e + 2 * p);
        float a0 = (lane < 16) ? e0.x : e0.y;
        uint2 u0 = *reinterpret_cast<const uint2*>(g_hh + (size_t)s0 * HC + lane * 4);
        float2 v0a = __half22float2(u32_to_h2(u0.x));
        float2 v0b = __half22float2(u32_to_h2(u0.y));
        acc0.x += a0 * v0a.x; acc0.y += a0 * v0a.y;
        acc0.z += a0 * v0b.x; acc0.w += a0 * v0b.y;
    }
    float4 acc = make_float4(acc0.x + acc1.x, acc0.y + acc1.y,
                             acc0.z + acc1.z, acc0.w + acc1.w);

    int j = lane * 4;
    float4 b = *reinterpret_cast<const float4*>(bias + j);
    float4 r = make_float4(acc.x + b.x, acc.y + b.y, acc.z + b.z, acc.w + b.w);
    if (FIRST) {
        float4 gm = *reinterpret_cast<const float4*>(gamma + j);
        float4 bt = *reinterpret_cast<const float4*>(beta + j);
        float4 mn = *reinterpret_cast<const float4*>(mean + j);
        float4 vr = *reinterpret_cast<const float4*>(var + j);
        r.x = (r.x - mn.x) * rsqrtf(vr.x + BN_EPS) * gm.x + bt.x;
        r.y = (r.y - mn.y) * rsqrtf(vr.y + BN_EPS) * gm.y + bt.y;
        r.z = (r.z - mn.z) * rsqrtf(vr.z + BN_EPS) * gm.z + bt.z;
        r.w = (r.w - mn.w) * rsqrtf(vr.w + BN_EPS) * gm.w + bt.w;
        r.x = r.x > 0.f ? r.x : expm1f(r.x);
        r.y = r.y > 0.f ? r.y : expm1f(r.y);
        r.z = r.z > 0.f ? r.z : expm1f(r.z);
        r.w = r.w > 0.f ? r.w : expm1f(r.w);
        *reinterpret_cast<float4*>(g_x1 + (size_t)w * HC + j) = r;
    } else {
        float4 p1 = *reinterpret_cast<const float4*>(g_x1 + (size_t)w * HC + j);
        r.x = fmaxf(r.x, p1.x); r.y = fmaxf(r.y, p1.y);
        r.z = fmaxf(r.z, p1.z); r.w = fmaxf(r.w, p1.w);        // JK 'max'
        *reinterpret_cast<float4*>(g_x2 + (size_t)w * HC + j) = r;
    }
}

// ------- head GEMM (M=64/block, Nc=40, K=128) + fused bias + log-softmax -----
__global__ __launch_bounds__(256)
void k_head(const float* __restrict__ A, const float* __restrict__ B,
            const float* __restrict__ bf, float* __restrict__ out, int M) {
    __shared__ __align__(16) float As[16][64];
    __shared__ __align__(16) float Bs[16][64];
    __shared__ float sred[64][17];
    __shared__ float srow[64];
    int t  = threadIdx.x;
    int tx = t & 15, ty = t >> 4;
    int rowBase = blockIdx.x * 64;

    float acc[4][4] = {};
    int aRow = t >> 2;
    int aK4  = (t & 3) * 4;
    int bK   = t >> 4;
    int bC4  = (t & 15) * 4;

    for (int k0 = 0; k0 < 128; k0 += 16) {
        float4 av = make_float4(0.f, 0.f, 0.f, 0.f);
        int gr = rowBase + aRow;
        if (gr < M) av = *reinterpret_cast<const float4*>(A + (size_t)gr * 128 + k0 + aK4);
        As[aK4 + 0][aRow] = av.x; As[aK4 + 1][aRow] = av.y;
        As[aK4 + 2][aRow] = av.z; As[aK4 + 3][aRow] = av.w;

        float4 bv = make_float4(0.f, 0.f, 0.f, 0.f);
        const float* brow = B + (size_t)(k0 + bK) * NOUTC;
        if (bC4 + 0 < NOUTC) bv.x = brow[bC4 + 0];
        if (bC4 + 1 < NOUTC) bv.y = brow[bC4 + 1];
        if (bC4 + 2 < NOUTC) bv.z = brow[bC4 + 2];
        if (bC4 + 3 < NOUTC) bv.w = brow[bC4 + 3];
        *reinterpret_cast<float4*>(&Bs[bK][bC4]) = bv;
        __syncthreads();

        #pragma unroll
        for (int k = 0; k < 16; k++) {
            float4 a4 = *reinterpret_cast<const float4*>(&As[k][ty * 4]);
            float4 b4 = *reinterpret_cast<const float4*>(&Bs[k][tx * 4]);
            float a[4] = {a4.x, a4.y, a4.z, a4.w};
            float b[4] = {b4.x, b4.y, b4.z, b4.w};
            #pragma unroll
            for (int i = 0; i < 4; i++)
                #pragma unroll
                for (int j = 0; j < 4; j++)
                    acc[i][j] += a[i] * b[j];
        }
        __syncthreads();
    }

    // add bias -> logits (cols tx*4+j, valid < 40)
    float bfv[4];
    #pragma unroll
    for (int j = 0; j < 4; j++)
        bfv[j] = (tx * 4 + j < NOUTC) ? bf[tx * 4 + j] : 0.f;
    #pragma unroll
    for (int i = 0; i < 4; i++)
        #pragma unroll
        for (int j = 0; j < 4; j++)
            acc[i][j] += bfv[j];

    // row max partials
    #pragma unroll
    for (int i = 0; i < 4; i++) {
        float pm = -3.0e38f;
        #pragma unroll
        for (int j = 0; j < 4; j++)
            if (tx * 4 + j < NOUTC) pm = fmaxf(pm, acc[i][j]);
        sred[ty * 4 + i][tx] = pm;
    }
    __syncthreads();
    if (t < 64) {
        float m = -3.0e38f;
        #pragma unroll
        for (int k = 0; k < 10; k++) m = fmaxf(m, sred[t][k]);
        srow[t] = m;
    }
    __syncthreads();
    // row sum partials
    #pragma unroll
    for (int i = 0; i < 4; i++) {
        float m = srow[ty * 4 + i];
        float ps = 0.f;
        #pragma unroll
        for (int j = 0; j < 4; j++)
            if (tx * 4 + j < NOUTC) ps += expf(acc[i][j] - m);
        sred[ty * 4 + i][tx] = ps;
    }
    __syncthreads();
    if (t < 64) {
        float s = 0.f;
        #pragma unroll
        for (int k = 0; k < 10; k++) s += sred[t][k];
        srow[t] += logf(s);           // lse
    }
    __syncthreads();

    #pragma unroll
    for (int i = 0; i < 4; i++) {
        int gr = rowBase + ty * 4 + i;
        if (gr >= M) continue;
        float lse = srow[ty * 4 + i];
        #pragma unroll
        for (int j = 0; j < 4; j++) {
            int gc = tx * 4 + j;
            if (gc < NOUTC) out[(size_t)gr * NOUTC + gc] = acc[i][j] - lse;
        }
    }
}

// ---------------- launch -----------------------------------------------------
extern "C" void kernel_launch(void* const* d_in, const int* in_sizes, int n_in,
                              void* d_out, int out_size) {
    const float* x     = (const float*)d_in[0];
    const void*  ei    = d_in[1];
    const float* W1    = (const float*)d_in[2];
    const float* as1   = (const float*)d_in[3];
    const float* ad1   = (const float*)d_in[4];
    const float* b1    = (const float*)d_in[5];
    const float* gamma = (const float*)d_in[6];
    const float* beta  = (const float*)d_in[7];
    const float* mean  = (const float*)d_in[8];
    const float* var   = (const float*)d_in[9];
    const float* W2    = (const float*)d_in[10];
    const float* as2   = (const float*)d_in[11];
    const float* ad2   = (const float*)d_in[12];
    const float* b2    = (const float*)d_in[13];
    const float* Wf    = (const float*)d_in[14];
    const float* bf    = (const float*)d_in[15];
    float* out = (float*)d_out;

    __half* hhP;
    float *x1P, *x2P;
    cudaGetSymbolAddress((void**)&hhP, g_hh);
    cudaGetSymbolAddress((void**)&x1P, g_x1);
    cudaGetSymbolAddress((void**)&x2P, g_x2);

    const int WPN = (NNODES * 32 + 255) / 256;   // warp-per-node grids

    k_init<<<(NNODES + 255) / 256, 256>>>((const int*)ei);
    k_count<<<(ETOT + 255) / 256, 256>>>(ei);
    k_scan1<<<NSCANB, 1024>>>();
    k_scan3<<<NSCANB, 1024>>>();
    k_fill<<<(ETOT + 255) / 256, 256>>>(ei);

    dim3 gemmG((NNODES + 127) / 128);

    // layer 1
    k_sgemm128<<<gemmG, 256>>>(x, W1, hhP, NNODES, as1, ad1);
    k_gat<true><<<WPN, 256>>>(b1, gamma, beta, mean, var);

    // layer 2
    k_sgemm128<<<gemmG, 256>>>(x1P, W2, hhP, NNODES, as2, ad2);
    k_gat<false><<<WPN, 256>>>(b2, nullptr, nullptr, nullptr, nullptr);

    // head: GEMM + bias + log-softmax fused
    k_head<<<(NNODES + 63) / 64, 256>>>(x2P, Wf, bf, out, NNODES);
}

// round 10
// speedup vs baseline: 1.3311x; 1.0639x over previous
#include <cuda_runtime.h>
#include <cuda_fp16.h>
#include <math.h>

#define NNODES 50000
#define NEDGES 800000
#define ETOT   (NEDGES + NNODES)
#define HC     128
#define NOUTC  40
#define NEG_SLOPE 0.2f
#define BN_EPS 1e-5f
#define NSCANB ((NNODES + 1023) / 1024)
#define FULLM 0xffffffffu

// ---------------- scratch (static device arrays; no runtime alloc) ----------
static __device__ __align__(16) __half g_hh[NNODES * HC];   // h in fp16 (gather)
static __device__ __align__(16) float g_x1[NNODES * HC];
static __device__ __align__(16) float g_x2[NNODES * HC];
static __device__ float g_asrc[NNODES * 2];
static __device__ float g_adst[NNODES * 2];
static __device__ __align__(16) float g_e[ETOT * 2];   // ex per edge (CSR order)
static __device__ int   g_deg[NNODES];
static __device__ int   g_rowptr[NNODES + 1];
static __device__ int   g_bsum[NSCANB + 1];
static __device__ int   g_tick[ETOT];
static __device__ int   g_csr_src[ETOT];
static __device__ int   g_is64;

// ---------------- half2 <-> u32 bit casts ------------------------------------
__device__ __forceinline__ unsigned int h2_to_u32(__half2 h) {
    return *reinterpret_cast<unsigned int*>(&h);
}
__device__ __forceinline__ __half2 u32_to_h2(unsigned int u) {
    return *reinterpret_cast<__half2*>(&u);
}

// ---------------- init: zero degrees + edge dtype detect ---------------------
__global__ void k_init(const int* ei32) {
    int i = blockIdx.x * blockDim.x + threadIdx.x;
    if (i < NNODES) g_deg[i] = 0;
    if (i == 0) {
        int any = 0;
        #pragma unroll 1
        for (int k = 0; k < 256; k++) any |= ei32[2 * k + 1];
        g_is64 = (any == 0) ? 1 : 0;   // int64 ids < 50000 -> high words all 0
    }
}

__device__ __forceinline__ int edge_idx(const void* ei, int pos) {
    if (g_is64) return (int)((const long long*)ei)[pos];
    return ((const int*)ei)[pos];
}

// ---------------- CSR build --------------------------------------------------
__global__ void k_count(const void* ei) {
    int i = blockIdx.x * blockDim.x + threadIdx.x;
    if (i >= ETOT) return;
    int d = (i < NEDGES) ? edge_idx(ei, NEDGES + i) : (i - NEDGES);
    g_tick[i] = atomicAdd(&g_deg[d], 1);
}

__global__ void k_scan1() {
    __shared__ int s[1024];
    int t = threadIdx.x;
    int idx = blockIdx.x * 1024 + t;
    int v = (idx < NNODES) ? g_deg[idx] : 0;
    s[t] = v;
    __syncthreads();
    #pragma unroll
    for (int o = 1; o < 1024; o <<= 1) {
        int add = (t >= o) ? s[t - o] : 0;
        __syncthreads();
        s[t] += add;
        __syncthreads();
    }
    if (idx < NNODES) g_rowptr[idx + 1] = s[t];
    if (t == 1023) g_bsum[blockIdx.x] = s[1023];
    if (idx == 0) g_rowptr[0] = 0;
}

// merged block-sum prefix + offset add (warp-parallel prefix per block)
__global__ void k_scan3() {
    __shared__ int pre;
    int b = blockIdx.x;
    if (threadIdx.x < 32) {
        int v = 0;
        if (threadIdx.x < b) v = g_bsum[threadIdx.x];
        if (threadIdx.x + 32 < b) v += g_bsum[threadIdx.x + 32];
        #pragma unroll
        for (int o = 16; o; o >>= 1) v += __shfl_xor_sync(FULLM, v, o);
        if (threadIdx.x == 0) pre = v;
    }
    __syncthreads();
    int idx = b * 1024 + threadIdx.x;
    if (idx < NNODES) g_rowptr[idx + 1] += pre;
}

__global__ void k_fill(const void* ei) {
    int i = blockIdx.x * blockDim.x + threadIdx.x;
    if (i >= ETOT) return;
    int s, d;
    if (i < NEDGES) { s = edge_idx(ei, i); d = edge_idx(ei, NEDGES + i); }
    else            { s = d = i - NEDGES; }
    g_csr_src[g_rowptr[d] + g_tick[i]] = s;   // atomic-free (ticket)
}

// ---------------- packed-f32x2 SGEMM (K=Nc=128), fp16 C, fused attn dots -----
__device__ __forceinline__ unsigned long long pack2(float a) {
    unsigned long long r;
    unsigned int u = __float_as_uint(a);
    asm("mov.b64 %0, {%1, %1};" : "=l"(r) : "r"(u));
    return r;
}
__device__ __forceinline__ float2 unpack2(unsigned long long v) {
    float2 f;
    asm("mov.b64 {%0, %1}, %2;" : "=f"(f.x), "=f"(f.y) : "l"(v));
    return f;
}

__global__ __launch_bounds__(256, 2)
void k_sgemm128(const float* __restrict__ A, const float* __restrict__ B,
                __half* __restrict__ C, int M,
                const float* __restrict__ att_src, const float* __restrict__ att_dst) {
    __shared__ __align__(16) float As[16][128];   // transposed A tile
    __shared__ __align__(16) float Bs[16][128];
    int t  = threadIdx.x;
    int tx = t & 15, ty = t >> 4;
    int rowBase = blockIdx.x * 128;

    unsigned long long acc[8][4];
    #pragma unroll
    for (int i = 0; i < 8; i++)
        #pragma unroll
        for (int j = 0; j < 4; j++) acc[i][j] = 0ull;

    int aRow = t >> 1;          // 0..127
    int aK   = (t & 1) * 8;     // 0 or 8
    int bRow = t >> 4;          // 0..15
    int bC   = (t & 15) * 8;    // 0..120

    for (int k0 = 0; k0 < 128; k0 += 16) {
        float4 av0 = make_float4(0.f, 0.f, 0.f, 0.f), av1 = av0;
        int gr = rowBase + aRow;
        if (gr < M) {
            const float* ap = A + (size_t)gr * 128 + k0 + aK;
            av0 = *reinterpret_cast<const float4*>(ap);
            av1 = *reinterpret_cast<const float4*>(ap + 4);
        }
        As[aK + 0][aRow] = av0.x; As[aK + 1][aRow] = av0.y;
        As[aK + 2][aRow] = av0.z; As[aK + 3][aRow] = av0.w;
        As[aK + 4][aRow] = av1.x; As[aK + 5][aRow] = av1.y;
        As[aK + 6][aRow] = av1.z; As[aK + 7][aRow] = av1.w;

        const float* bp = B + (size_t)(k0 + bRow) * 128 + bC;
        *reinterpret_cast<float4*>(&Bs[bRow][bC])     = *reinterpret_cast<const float4*>(bp);
        *reinterpret_cast<float4*>(&Bs[bRow][bC + 4]) = *reinterpret_cast<const float4*>(bp + 4);
        __syncthreads();

        #pragma unroll
        for (int k = 0; k < 16; k++) {
            float4 a0 = *reinterpret_cast<const float4*>(&As[k][ty * 8]);
            float4 a1 = *reinterpret_cast<const float4*>(&As[k][ty * 8 + 4]);
            unsigned long long aa[8];
            aa[0] = pack2(a0.x); aa[1] = pack2(a0.y); aa[2] = pack2(a0.z); aa[3] = pack2(a0.w);
            aa[4] = pack2(a1.x); aa[5] = pack2(a1.y); aa[6] = pack2(a1.z); aa[7] = pack2(a1.w);
            const unsigned long long* bpp =
                reinterpret_cast<const unsigned long long*>(&Bs[k][tx * 8]);
            unsigned long long b0 = bpp[0], b1 = bpp[1], b2 = bpp[2], b3 = bpp[3];
            #pragma unroll
            for (int i = 0; i < 8; i++) {
                asm("fma.rn.f32x2 %0, %1, %2, %0;" : "+l"(acc[i][0]) : "l"(aa[i]), "l"(b0));
                asm("fma.rn.f32x2 %0, %1, %2, %0;" : "+l"(acc[i][1]) : "l"(aa[i]), "l"(b1));
                asm("fma.rn.f32x2 %0, %1, %2, %0;" : "+l"(acc[i][2]) : "l"(aa[i]), "l"(b2));
                asm("fma.rn.f32x2 %0, %1, %2, %0;" : "+l"(acc[i][3]) : "l"(aa[i]), "l"(b3));
            }
        }
        __syncthreads();
    }

    // store C as fp16 (8 cols = 4 half2 = 16 B per thread-row)
    #pragma unroll
    for (int i = 0; i < 8; i++) {
        int gr = rowBase + ty * 8 + i;
        if (gr >= M) continue;
        uint4 pk;
        float2 c0 = unpack2(acc[i][0]);
        float2 c1 = unpack2(acc[i][1]);
        float2 c2 = unpack2(acc[i][2]);
        float2 c3 = unpack2(acc[i][3]);
        pk.x = h2_to_u32(__float22half2_rn(c0));
        pk.y = h2_to_u32(__float22half2_rn(c1));
        pk.z = h2_to_u32(__float22half2_rn(c2));
        pk.w = h2_to_u32(__float22half2_rn(c3));
        *reinterpret_cast<uint4*>(C + (size_t)gr * 128 + tx * 8) = pk;
    }

    // fused attention dot-products (fp32 accumulators)
    float asv[8], adv[8];
    #pragma unroll
    for (int j = 0; j < 8; j++) {
        asv[j] = att_src[tx * 8 + j];
        adv[j] = att_dst[tx * 8 + j];
    }
    float* sredS = &As[0][0];   // [128][16]
    float* sredD = &Bs[0][0];
    #pragma unroll
    for (int i = 0; i < 8; i++) {
        float ps = 0.f, pd = 0.f;
        #pragma unroll
        for (int j = 0; j < 4; j++) {
            float2 c = unpack2(acc[i][j]);
            ps += c.x * asv[2 * j] + c.y * asv[2 * j + 1];
            pd += c.x * adv[2 * j] + c.y * adv[2 * j + 1];
        }
        int row = ty * 8 + i;
        sredS[row * 16 + tx] = ps;
        sredD[row * 16 + tx] = pd;
    }
    __syncthreads();
    {
        int row  = t >> 1;
        int half = t & 1;
        int gr = rowBase + row;
        if (gr < M) {
            float ss = 0.f, sd = 0.f;
            #pragma unroll
            for (int k = 0; k < 8; k++) {
                ss += sredS[row * 16 + half * 8 + k];
                sd += sredD[row * 16 + half * 8 + k];
            }
            g_asrc[gr * 2 + half] = ss;
            g_adst[gr * 2 + half] = sd;
        }
    }
}

// ------- fused softmax + aggregate: 2 passes, no max-shift, fast exp ---------
// softmax is shift-invariant; |e| <= ~10 here so exp(e) is safe in fp32.
template <bool FIRST>
__global__ __launch_bounds__(256)
void k_gat(const float* __restrict__ bias,
           const float* __restrict__ gamma, const float* __restrict__ beta,
           const float* __restrict__ mean,  const float* __restrict__ var) {
    int gt = blockIdx.x * blockDim.x + threadIdx.x;
    int w = gt >> 5, lane = gt & 31;
    if (w >= NNODES) return;
    int beg = g_rowptr[w], end = g_rowptr[w + 1];
    float ad0 = g_adst[w * 2], ad1 = g_adst[w * 2 + 1];

    // pass 1: ex = exp(leaky(e)), store; accumulate denominator (lane-strided)
    float s0 = 0.f, s1 = 0.f;
    for (int p = beg + lane; p < end; p += 32) {
        int s = g_csr_src[p];
        float2 av = *reinterpret_cast<const float2*>(g_asrc + 2 * s);
        float e0 = av.x + ad0;
        float e1 = av.y + ad1;
        e0 = e0 > 0.f ? e0 : NEG_SLOPE * e0;
        e1 = e1 > 0.f ? e1 : NEG_SLOPE * e1;
        float x0 = __expf(e0);
        float x1 = __expf(e1);
        float2 ev; ev.x = x0; ev.y = x1;
        *reinterpret_cast<float2*>(g_e + 2 * p) = ev;
        s0 += x0; s1 += x1;
    }
    #pragma unroll
    for (int o = 16; o; o >>= 1) {
        s0 += __shfl_xor_sync(FULLM, s0, o);
        s1 += __shfl_xor_sync(FULLM, s1, o);
    }
    float inv0 = 1.f / (s0 + 1e-16f);
    float inv1 = 1.f / (s1 + 1e-16f);
    float invh = (lane < 16) ? inv0 : inv1;
    __syncwarp();

    // pass 2: fp16 gather with broadcast ex * inv, dual accumulators for MLP
    float4 acc0 = make_float4(0.f, 0.f, 0.f, 0.f);
    float4 acc1 = make_float4(0.f, 0.f, 0.f, 0.f);
    int p = beg;
    for (; p + 1 < end; p += 2) {
        int s0i = g_csr_src[p];
        int s1i = g_csr_src[p + 1];
        float2 e0 = *reinterpret_cast<const float2*>(g_e + 2 * p);
        float2 e1 = *reinterpret_cast<const float2*>(g_e + 2 * (p + 1));
        float a0 = ((lane < 16) ? e0.x : e0.y) * invh;
        float a1 = ((lane < 16) ? e1.x : e1.y) * invh;
        uint2 u0 = *reinterpret_cast<const uint2*>(g_hh + (size_t)s0i * HC + lane * 4);
        uint2 u1 = *reinterpret_cast<const uint2*>(g_hh + (size_t)s1i * HC + lane * 4);
        float2 v0a = __half22float2(u32_to_h2(u0.x));
        float2 v0b = __half22float2(u32_to_h2(u0.y));
        float2 v1a = __half22float2(u32_to_h2(u1.x));
        float2 v1b = __half22float2(u32_to_h2(u1.y));
        acc0.x += a0 * v0a.x; acc0.y += a0 * v0a.y;
        acc0.z += a0 * v0b.x; acc0.w += a0 * v0b.y;
        acc1.x += a1 * v1a.x; acc1.y += a1 * v1a.y;
        acc1.z += a1 * v1b.x; acc1.w += a1 * v1b.y;
    }
    if (p < end) {
        int s0i = g_csr_src[p];
        float2 e0 = *reinterpret_cast<const float2*>(g_e + 2 * p);
        float a0 = ((lane < 16) ? e0.x : e0.y) * invh;
        uint2 u0 = *reinterpret_cast<const uint2*>(g_hh + (size_t)s0i * HC + lane * 4);
        float2 v0a = __half22float2(u32_to_h2(u0.x));
        float2 v0b = __half22float2(u32_to_h2(u0.y));
        acc0.x += a0 * v0a.x; acc0.y += a0 * v0a.y;
        acc0.z += a0 * v0b.x; acc0.w += a0 * v0b.y;
    }
    float4 acc = make_float4(acc0.x + acc1.x, acc0.y + acc1.y,
                             acc0.z + acc1.z, acc0.w + acc1.w);

    int j = lane * 4;
    float4 b = *reinterpret_cast<const float4*>(bias + j);
    float4 r = make_float4(acc.x + b.x, acc.y + b.y, acc.z + b.z, acc.w + b.w);
    if (FIRST) {
        float4 gm = *reinterpret_cast<const float4*>(gamma + j);
        float4 bt = *reinterpret_cast<const float4*>(beta + j);
        float4 mn = *reinterpret_cast<const float4*>(mean + j);
        float4 vr = *reinterpret_cast<const float4*>(var + j);
        r.x = (r.x - mn.x) * rsqrtf(vr.x + BN_EPS) * gm.x + bt.x;
        r.y = (r.y - mn.y) * rsqrtf(vr.y + BN_EPS) * gm.y + bt.y;
        r.z = (r.z - mn.z) * rsqrtf(vr.z + BN_EPS) * gm.z + bt.z;
        r.w = (r.w - mn.w) * rsqrtf(vr.w + BN_EPS) * gm.w + bt.w;
        r.x = r.x > 0.f ? r.x : expm1f(r.x);
        r.y = r.y > 0.f ? r.y : expm1f(r.y);
        r.z = r.z > 0.f ? r.z : expm1f(r.z);
        r.w = r.w > 0.f ? r.w : expm1f(r.w);
        *reinterpret_cast<float4*>(g_x1 + (size_t)w * HC + j) = r;
    } else {
        float4 p1 = *reinterpret_cast<const float4*>(g_x1 + (size_t)w * HC + j);
        r.x = fmaxf(r.x, p1.x); r.y = fmaxf(r.y, p1.y);
        r.z = fmaxf(r.z, p1.z); r.w = fmaxf(r.w, p1.w);        // JK 'max'
        *reinterpret_cast<float4*>(g_x2 + (size_t)w * HC + j) = r;
    }
}

// ------- head GEMM (M=64/block, Nc=40, K=128) + fused bias + log-softmax -----
__global__ __launch_bounds__(256)
void k_head(const float* __restrict__ A, const float* __restrict__ B,
            const float* __restrict__ bf, float* __restrict__ out, int M) {
    __shared__ __align__(16) float As[16][64];
    __shared__ __align__(16) float Bs[16][64];
    __shared__ float sred[64][17];
    __shared__ float srow[64];
    int t  = threadIdx.x;
    int tx = t & 15, ty = t >> 4;
    int rowBase = blockIdx.x * 64;

    float acc[4][4] = {};
    int aRow = t >> 2;
    int aK4  = (t & 3) * 4;
    int bK   = t >> 4;
    int bC4  = (t & 15) * 4;

    for (int k0 = 0; k0 < 128; k0 += 16) {
        float4 av = make_float4(0.f, 0.f, 0.f, 0.f);
        int gr = rowBase + aRow;
        if (gr < M) av = *reinterpret_cast<const float4*>(A + (size_t)gr * 128 + k0 + aK4);
        As[aK4 + 0][aRow] = av.x; As[aK4 + 1][aRow] = av.y;
        As[aK4 + 2][aRow] = av.z; As[aK4 + 3][aRow] = av.w;

        float4 bv = make_float4(0.f, 0.f, 0.f, 0.f);
        const float* brow = B + (size_t)(k0 + bK) * NOUTC;
        if (bC4 + 0 < NOUTC) bv.x = brow[bC4 + 0];
        if (bC4 + 1 < NOUTC) bv.y = brow[bC4 + 1];
        if (bC4 + 2 < NOUTC) bv.z = brow[bC4 + 2];
        if (bC4 + 3 < NOUTC) bv.w = brow[bC4 + 3];
        *reinterpret_cast<float4*>(&Bs[bK][bC4]) = bv;
        __syncthreads();

        #pragma unroll
        for (int k = 0; k < 16; k++) {
            float4 a4 = *reinterpret_cast<const float4*>(&As[k][ty * 4]);
            float4 b4 = *reinterpret_cast<const float4*>(&Bs[k][tx * 4]);
            float a[4] = {a4.x, a4.y, a4.z, a4.w};
            float b[4] = {b4.x, b4.y, b4.z, b4.w};
            #pragma unroll
            for (int i = 0; i < 4; i++)
                #pragma unroll
                for (int j = 0; j < 4; j++)
                    acc[i][j] += a[i] * b[j];
        }
        __syncthreads();
    }

    // add bias -> logits (cols tx*4+j, valid < 40)
    float bfv[4];
    #pragma unroll
    for (int j = 0; j < 4; j++)
        bfv[j] = (tx * 4 + j < NOUTC) ? bf[tx * 4 + j] : 0.f;
    #pragma unroll
    for (int i = 0; i < 4; i++)
        #pragma unroll
        for (int j = 0; j < 4; j++)
            acc[i][j] += bfv[j];

    // row max partials
    #pragma unroll
    for (int i = 0; i < 4; i++) {
        float pm = -3.0e38f;
        #pragma unroll
        for (int j = 0; j < 4; j++)
            if (tx * 4 + j < NOUTC) pm = fmaxf(pm, acc[i][j]);
        sred[ty * 4 + i][tx] = pm;
    }
    __syncthreads();
    if (t < 64) {
        float m = -3.0e38f;
        #pragma unroll
        for (int k = 0; k < 10; k++) m = fmaxf(m, sred[t][k]);
        srow[t] = m;
    }
    __syncthreads();
    // row sum partials
    #pragma unroll
    for (int i = 0; i < 4; i++) {
        float m = srow[ty * 4 + i];
        float ps = 0.f;
        #pragma unroll
        for (int j = 0; j < 4; j++)
            if (tx * 4 + j < NOUTC) ps += expf(acc[i][j] - m);
        sred[ty * 4 + i][tx] = ps;
    }
    __syncthreads();
    if (t < 64) {
        float s = 0.f;
        #pragma unroll
        for (int k = 0; k < 10; k++) s += sred[t][k];
        srow[t] += logf(s);           // lse
    }
    __syncthreads();

    #pragma unroll
    for (int i = 0; i < 4; i++) {
        int gr = rowBase + ty * 4 + i;
        if (gr >= M) continue;
        float lse = srow[ty * 4 + i];
        #pragma unroll
        for (int j = 0; j < 4; j++) {
            int gc = tx * 4 + j;
            if (gc < NOUTC) out[(size_t)gr * NOUTC + gc] = acc[i][j] - lse;
        }
    }
}

// ---------------- launch -----------------------------------------------------
extern "C" void kernel_launch(void* const* d_in, const int* in_sizes, int n_in,
                              void* d_out, int out_size) {
    const float* x     = (const float*)d_in[0];
    const void*  ei    = d_in[1];
    const float* W1    = (const float*)d_in[2];
    const float* as1   = (const float*)d_in[3];
    const float* ad1   = (const float*)d_in[4];
    const float* b1    = (const float*)d_in[5];
    const float* gamma = (const float*)d_in[6];
    const float* beta  = (const float*)d_in[7];
    const float* mean  = (const float*)d_in[8];
    const float* var   = (const float*)d_in[9];
    const float* W2    = (const float*)d_in[10];
    const float* as2   = (const float*)d_in[11];
    const float* ad2   = (const float*)d_in[12];
    const float* b2    = (const float*)d_in[13];
    const float* Wf    = (const float*)d_in[14];
    const float* bf    = (const float*)d_in[15];
    float* out = (float*)d_out;

    __half* hhP;
    float *x1P, *x2P;
    cudaGetSymbolAddress((void**)&hhP, g_hh);
    cudaGetSymbolAddress((void**)&x1P, g_x1);
    cudaGetSymbolAddress((void**)&x2P, g_x2);

    const int WPN = (NNODES * 32 + 255) / 256;   // warp-per-node grids

    k_init<<<(NNODES + 255) / 256, 256>>>((const int*)ei);
    k_count<<<(ETOT + 255) / 256, 256>>>(ei);
    k_scan1<<<NSCANB, 1024>>>();
    k_scan3<<<NSCANB, 1024>>>();
    k_fill<<<(ETOT + 255) / 256, 256>>>(ei);

    dim3 gemmG((NNODES + 127) / 128);

    // layer 1
    k_sgemm128<<<gemmG, 256>>>(x, W1, hhP, NNODES, as1, ad1);
    k_gat<true><<<WPN, 256>>>(b1, gamma, beta, mean, var);

    // layer 2
    k_sgemm128<<<gemmG, 256>>>(x1P, W2, hhP, NNODES, as2, ad2);
    k_gat<false><<<WPN, 256>>>(b2, nullptr, nullptr, nullptr, nullptr);

    // head: GEMM + bias + log-softmax fused
    k_head<<<(NNODES + 63) / 64, 256>>>(x2P, Wf, bf, out, NNODES);
}